// round 1
// baseline (speedup 1.0000x reference)
#include <cuda_runtime.h>
#include <cstdint>
#include <cstddef>

#define NROWS 131072
#define NDENSE 13
#define NSPARSE 26
#define NFIELD 39
#define EMBD 16
#define DDIM 624
#define HID 32
#define VOCABSZ 100000
#define EPSV 1e-5f

// ---- scratch (static device globals; no allocation) ----
__device__ float g_x1[(size_t)HID * NROWS];   // column-major [HID][NROWS]
__device__ float g_rest[NROWS];
__device__ float g_S1[HID];
__device__ float g_S2[HID * HID];
__device__ float g_u[HID];
__device__ float g_c0;
__device__ float g_A2[NDENSE * HID];
__device__ float g_B2[NDENSE * HID];
__device__ float g_w1s[NDENSE];
__device__ float g_b1s[NDENSE];

// ---- packed f32x2 helpers (Blackwell) ----
__device__ __forceinline__ unsigned long long pk2(float a, float b) {
    unsigned long long r;
    asm("mov.b64 %0, {%1, %2};" : "=l"(r)
        : "r"(__float_as_uint(a)), "r"(__float_as_uint(b)));
    return r;
}
__device__ __forceinline__ void upk2(unsigned long long v, float& a, float& b) {
    unsigned int x, y;
    asm("mov.b64 {%0, %1}, %2;" : "=r"(x), "=r"(y) : "l"(v));
    a = __uint_as_float(x); b = __uint_as_float(y);
}
__device__ __forceinline__ unsigned long long fma2(unsigned long long a,
                                                   unsigned long long b,
                                                   unsigned long long c) {
    unsigned long long d;
    asm("fma.rn.f32x2 %0, %1, %2, %3;" : "=l"(d) : "l"(a), "l"(b), "l"(c));
    return d;
}

// ---- K0: fold dense projections, zero stats ----
__global__ void pre_kernel(const float* __restrict__ W1d, const float* __restrict__ b1d,
                           const float* __restrict__ W2d, const float* __restrict__ b2d,
                           const float* __restrict__ Wl1) {
    int t = threadIdx.x;
    if (t < NDENSE * HID) {
        int f = t >> 5, j = t & 31;
        float a = 0.f, b = 0.f;
        #pragma unroll
        for (int e = 0; e < EMBD; e++) {
            float w = Wl1[(f * EMBD + e) * HID + j];
            a = fmaf(W2d[f * EMBD + e], w, a);
            b = fmaf(b2d[f * EMBD + e], w, b);
        }
        g_A2[t] = a; g_B2[t] = b;
    }
    if (t < NDENSE) {
        float a = 0.f, b = 0.f;
        #pragma unroll
        for (int e = 0; e < EMBD; e++) { a += W1d[t * EMBD + e]; b += b1d[t * EMBD + e]; }
        g_w1s[t] = a; g_b1s[t] = b;
    }
    if (t < HID) g_S1[t] = 0.f;
    if (t < HID * HID) g_S2[t] = 0.f;
}

// ---- K1: fused embed + FM + deep@Wl1 (thread-per-row) ----
__global__ __launch_bounds__(256, 2) void main_kernel(
    const float* __restrict__ Xi_dense, const int* __restrict__ Xi_sparse,
    const float* __restrict__ Xv, const float* __restrict__ bias,
    const float* __restrict__ T1, const float* __restrict__ T2,
    const float* __restrict__ W2d, const float* __restrict__ b2d,
    const float* __restrict__ Wl1, const float* __restrict__ bl1)
{
    extern __shared__ float sm[];
    float* sWl1 = sm;                          // 19968
    float* sA2  = sWl1 + DDIM * HID;           // 416
    float* sB2  = sA2 + NDENSE * HID;          // 416
    float* sW2  = sB2 + NDENSE * HID;          // 208
    float* sb2  = sW2 + NDENSE * EMBD;         // 208
    float* sw1  = sb2 + NDENSE * EMBD;         // 13
    float* sb1  = sw1 + NDENSE;                // 13
    float* sbl  = sb1 + NDENSE;                // 32

    for (int i = threadIdx.x; i < DDIM * HID; i += blockDim.x) sWl1[i] = Wl1[i];
    for (int i = threadIdx.x; i < NDENSE * HID; i += blockDim.x) { sA2[i] = g_A2[i]; sB2[i] = g_B2[i]; }
    for (int i = threadIdx.x; i < NDENSE * EMBD; i += blockDim.x) { sW2[i] = W2d[i]; sb2[i] = b2d[i]; }
    if (threadIdx.x < NDENSE) { sw1[threadIdx.x] = g_w1s[threadIdx.x]; sb1[threadIdx.x] = g_b1s[threadIdx.x]; }
    if (threadIdx.x < HID) sbl[threadIdx.x] = bl1[threadIdx.x];
    __syncthreads();

    int n = blockIdx.x * blockDim.x + threadIdx.x;
    if (n >= NROWS) return;

    unsigned long long x1p[16];
    #pragma unroll
    for (int i = 0; i < 16; i++) x1p[i] = 0ull;
    float s[EMBD];
    #pragma unroll
    for (int e = 0; e < EMBD; e++) s[e] = 0.f;
    float sqsum = 0.f;
    float rest = bias[n];

    const float* xv = Xv + (size_t)n * NFIELD;
    const float* xd = Xi_dense + (size_t)n * NDENSE;
    const int*   xs = Xi_sparse + (size_t)n * NSPARSE;

    // dense fields: first via folded sums, x1 via A2/B2, FM explicit
    for (int f = 0; f < NDENSE; f++) {
        float v = xv[f];
        float xi = xd[f];
        rest = fmaf(v, fmaf(xi, sw1[f], sb1[f]), rest);
        float xiv = xi * v;
        unsigned long long xivp = pk2(xiv, xiv);
        unsigned long long vp = pk2(v, v);
        const unsigned long long* A = (const unsigned long long*)(sA2 + f * HID);
        const unsigned long long* B = (const unsigned long long*)(sB2 + f * HID);
        #pragma unroll
        for (int jp = 0; jp < 16; jp++) {
            x1p[jp] = fma2(xivp, A[jp], x1p[jp]);
            x1p[jp] = fma2(vp,   B[jp], x1p[jp]);
        }
        #pragma unroll
        for (int e = 0; e < EMBD; e++) {
            float t = fmaf(xi, sW2[f * EMBD + e], sb2[f * EMBD + e]) * v;
            s[e] += t;
            sqsum = fmaf(t, t, sqsum);
        }
    }

    // sparse fields: gather 64B from T1 & T2, FM + projection
    for (int f = 0; f < NSPARSE; f++) {
        float v = xv[NDENSE + f];
        size_t base = ((size_t)f * VOCABSZ + (size_t)xs[f]) * EMBD;
        const float4* p1 = (const float4*)(T1 + base);
        const float4* p2 = (const float4*)(T2 + base);
        float4 a0 = p1[0], a1 = p1[1], a2 = p1[2], a3 = p1[3];
        float4 b0 = p2[0], b1 = p2[1], b2 = p2[2], b3 = p2[3];
        float fs = ((a0.x + a0.y) + (a0.z + a0.w)) + ((a1.x + a1.y) + (a1.z + a1.w))
                 + ((a2.x + a2.y) + (a2.z + a2.w)) + ((a3.x + a3.y) + (a3.z + a3.w));
        rest = fmaf(v, fs, rest);
        float tv[16];
        tv[0] = b0.x * v;  tv[1] = b0.y * v;  tv[2] = b0.z * v;  tv[3] = b0.w * v;
        tv[4] = b1.x * v;  tv[5] = b1.y * v;  tv[6] = b1.z * v;  tv[7] = b1.w * v;
        tv[8] = b2.x * v;  tv[9] = b2.y * v;  tv[10] = b2.z * v; tv[11] = b2.w * v;
        tv[12] = b3.x * v; tv[13] = b3.y * v; tv[14] = b3.z * v; tv[15] = b3.w * v;
        #pragma unroll
        for (int e = 0; e < EMBD; e++) {
            s[e] += tv[e];
            sqsum = fmaf(tv[e], tv[e], sqsum);
        }
        const float* wrowbase = sWl1 + (NDENSE * EMBD + f * EMBD) * HID;
        #pragma unroll
        for (int e = 0; e < EMBD; e++) {
            unsigned long long te = pk2(tv[e], tv[e]);
            const ulonglong2* w = (const ulonglong2*)(wrowbase + e * HID);
            #pragma unroll
            for (int q = 0; q < 8; q++) {
                ulonglong2 ww = w[q];
                x1p[2 * q]     = fma2(te, ww.x, x1p[2 * q]);
                x1p[2 * q + 1] = fma2(te, ww.y, x1p[2 * q + 1]);
            }
        }
    }

    float fm = 0.f;
    #pragma unroll
    for (int e = 0; e < EMBD; e++) fm = fmaf(s[e], s[e], fm);
    rest += 0.5f * (fm - sqsum);
    g_rest[n] = rest;

    // store x1 column-major (fully coalesced), adding bl1
    #pragma unroll
    for (int jp = 0; jp < 16; jp++) {
        float lo, hi; upk2(x1p[jp], lo, hi);
        g_x1[(size_t)(2 * jp) * NROWS + n]     = lo + sbl[2 * jp];
        g_x1[(size_t)(2 * jp + 1) * NROWS + n] = hi + sbl[2 * jp + 1];
    }
}

// ---- K2: S1 and full S2 = sum x1 x1^T (32x32) ----
__global__ __launch_bounds__(1024) void stats_kernel() {
    __shared__ float tile[HID][257];
    int k = threadIdx.x >> 5;
    int l = threadIdx.x & 31;
    float acc = 0.f, acc1 = 0.f;
    for (int chunk = blockIdx.x; chunk < NROWS / 256; chunk += gridDim.x) {
        int r0 = chunk * 256;
        #pragma unroll
        for (int i = 0; i < 8; i++) {
            int idx = threadIdx.x + i * 1024;
            int col = idx >> 8;
            int r = idx & 255;
            tile[col][r] = g_x1[(size_t)col * NROWS + r0 + r];
        }
        __syncthreads();
        #pragma unroll 8
        for (int r = 0; r < 256; r++) {
            float xk = tile[k][r];
            float xl = tile[l][r];
            acc = fmaf(xk, xl, acc);
            acc1 += xk;
        }
        __syncthreads();
    }
    atomicAdd(&g_S2[k * HID + l], acc);
    if (l == 0) atomicAdd(&g_S1[k], acc1);
}

// ---- K3: closed-form BN folding -> u[32], c0 ----
__global__ void fin_kernel(const float* __restrict__ g1, const float* __restrict__ be1,
                           const float* __restrict__ Wl2, const float* __restrict__ bl2,
                           const float* __restrict__ g2, const float* __restrict__ be2) {
    __shared__ float a1s[HID], m1s[HID], a2s[HID];
    __shared__ float qv[HID][HID + 1];
    int j = threadIdx.x;
    const float invN = 1.f / (float)NROWS;
    float m1 = g_S1[j] * invN;
    float v1 = g_S2[j * HID + j] * invN - m1 * m1;
    float a1 = g1[j] * rsqrtf(v1 + EPSV);
    a1s[j] = a1; m1s[j] = m1;
    __syncthreads();
    for (int k = 0; k < HID; k++) qv[k][j] = a1s[k] * Wl2[k * HID + j];
    __syncthreads();
    float vy = 0.f;
    for (int k = 0; k < HID; k++) {
        float qk = qv[k][j];
        float mk = m1s[k];
        for (int l = 0; l < HID; l++) {
            float c = g_S2[k * HID + l] * invN - mk * m1s[l];
            vy = fmaf(qk * qv[l][j], c, vy);
        }
    }
    float my = bl2[j];
    for (int k = 0; k < HID; k++) my = fmaf(be1[k], Wl2[k * HID + j], my);
    float a2 = g2[j] * rsqrtf(vy + EPSV);
    a2s[j] = a2;
    float cpart = fmaf(a2, bl2[j] - my, be2[j]);
    __syncthreads();
    // thread j plays role of k for w~ = Wl2 @ a2
    float wt = 0.f;
    for (int jj = 0; jj < HID; jj++) wt = fmaf(Wl2[j * HID + jj], a2s[jj], wt);
    g_u[j] = a1 * wt;
    cpart = fmaf(be1[j] - a1 * m1, wt, cpart);
    #pragma unroll
    for (int off = 16; off > 0; off >>= 1) cpart += __shfl_down_sync(0xffffffffu, cpart, off);
    if (j == 0) g_c0 = cpart;
}

// ---- K4: out = rest + x1 . u + c0 ----
__global__ __launch_bounds__(256) void out_kernel(float* __restrict__ out) {
    __shared__ float us[HID];
    __shared__ float c0s;
    if (threadIdx.x < HID) us[threadIdx.x] = g_u[threadIdx.x];
    if (threadIdx.x == HID) c0s = g_c0;
    __syncthreads();
    int n = blockIdx.x * blockDim.x + threadIdx.x;
    if (n >= NROWS) return;
    float acc = g_rest[n] + c0s;
    #pragma unroll
    for (int j = 0; j < HID; j++)
        acc = fmaf(g_x1[(size_t)j * NROWS + n], us[j], acc);
    out[n] = acc;
}

extern "C" void kernel_launch(void* const* d_in, const int* in_sizes, int n_in,
                              void* d_out, int out_size) {
    const float* Xi_dense  = (const float*)d_in[0];
    const int*   Xi_sparse = (const int*)d_in[1];
    const float* Xv   = (const float*)d_in[2];
    const float* bias = (const float*)d_in[3];
    const float* W1d  = (const float*)d_in[4];
    const float* b1d  = (const float*)d_in[5];
    const float* T1   = (const float*)d_in[6];
    const float* W2d  = (const float*)d_in[7];
    const float* b2d  = (const float*)d_in[8];
    const float* T2   = (const float*)d_in[9];
    const float* Wl1  = (const float*)d_in[10];
    const float* bl1  = (const float*)d_in[11];
    const float* g1   = (const float*)d_in[12];
    const float* be1  = (const float*)d_in[13];
    const float* Wl2  = (const float*)d_in[14];
    const float* bl2  = (const float*)d_in[15];
    const float* g2   = (const float*)d_in[16];
    const float* be2  = (const float*)d_in[17];
    float* out = (float*)d_out;

    size_t smem = (size_t)(DDIM * HID + 2 * NDENSE * HID + 2 * NDENSE * EMBD
                           + 2 * NDENSE + HID) * sizeof(float);
    cudaFuncSetAttribute(main_kernel, cudaFuncAttributeMaxDynamicSharedMemorySize, (int)smem);

    pre_kernel<<<1, 1024>>>(W1d, b1d, W2d, b2d, Wl1);
    main_kernel<<<NROWS / 256, 256, smem>>>(Xi_dense, Xi_sparse, Xv, bias,
                                            T1, T2, W2d, b2d, Wl1, bl1);
    stats_kernel<<<256, 1024>>>();
    fin_kernel<<<1, HID>>>(g1, be1, Wl2, bl2, g2, be2);
    out_kernel<<<NROWS / 256, 256>>>(out);
}